// round 1
// baseline (speedup 1.0000x reference)
#include <cuda_runtime.h>
#include <cuda_bf16.h>

#define NBINS 10
#define NCLS  128
#define NLAB  (NCLS * 3)   // 384

// ---------------- device scratch (zeroed each launch by init kernel) ----------------
__device__ float g_loss;
__device__ float g_msum;
__device__ float g_gd[NBINS];
__device__ float g_lab[NLAB];

__global__ void ghm_init_kernel() {
    int t = threadIdx.x;
    if (t == 0) { g_loss = 0.f; g_msum = 0.f; }
    if (t < NBINS) g_gd[t] = 0.f;
    for (int i = t; i < NLAB; i += blockDim.x) g_lab[i] = 0.f;
}

// ---------------- main kernel: warp per row of 128 classes ----------------
// lane l handles classes 4l..4l+3 (one float4 of logits + one of targets).
__global__ __launch_bounds__(256)
void ghm_main_kernel(const float4* __restrict__ logits,
                     const float4* __restrict__ tprob,
                     const float*  __restrict__ mask,
                     const float*  __restrict__ gd_ema,
                     const float*  __restrict__ lab_ema,
                     int rows)
{
    __shared__ float s_gd[NBINS];          // rsqrt(GD_ema)
    __shared__ float s_lab[NLAB];          // rsqrt(label_ema)
    __shared__ float s_lab_stage[8 * 416]; // per-warp label hist, lane stride 13 (conflict-free)
    __shared__ float s_gd_stage[8 * NBINS];
    __shared__ float s_loss[8], s_m[8];

    const int tid  = threadIdx.x;
    const int lane = tid & 31;
    const int warp = tid >> 5;

    if (tid < NBINS) s_gd[tid] = rsqrtf(gd_ema[tid]);
    for (int i = tid; i < NLAB; i += 256) s_lab[i] = rsqrtf(lab_ema[i]);
    __syncthreads();

    const int gwarp  = blockIdx.x * 8 + warp;
    const int nwarps = gridDim.x * 8;

    float loss_acc = 0.f;
    float m_acc    = 0.f;    // one m per row per lane (covers 4 elements -> scale x4 at end)
    float gd_acc[NBINS];
    float lab_acc[12];
#pragma unroll
    for (int b = 0; b < NBINS; b++) gd_acc[b] = 0.f;
#pragma unroll
    for (int k = 0; k < 12; k++) lab_acc[k] = 0.f;

    // base smem index for this lane's label weights: class c = 4*lane + e, tpi = 3*c + tb
    const int lab_base = 12 * lane;

    for (int row = gwarp; row < rows; row += nwarps) {
        const float4 x4 = logits[(long long)row * 32 + lane];
        const float4 t4 = tprob [(long long)row * 32 + lane];
        const float  m  = __ldg(&mask[row]);
        m_acc += m;

        float xs[4] = {x4.x, x4.y, x4.z, x4.w};
        float ts[4] = {t4.x, t4.y, t4.z, t4.w};

#pragma unroll
        for (int e = 0; e < 4; e++) {
            float x = xs[e];
            float t = fminf(fmaxf(ts[e], 0.f), 1.f);

            float ax = fabsf(x);
            float ee = __expf(-ax);                 // exp(-|x|), in (0,1]
            float r  = __frcp_rn(1.f + ee);
            float sig = (x >= 0.f) ? r : ee * r;    // sigmoid(x)
            float raw = fmaxf(x, 0.f) - x * t + __logf(1.f + ee); // stable BCE
            float g   = fabsf(sig - t);

            int bi = (int)(g * 10.f);  bi = min(bi, NBINS - 1);
            int tb = (int)(t * 3.f);   tb = min(tb, 2);

            float w = s_gd[bi] * s_lab[lab_base + 3 * e + tb];
            loss_acc = fmaf(raw * w, m, loss_acc);

            // GD histogram: static-index predicated adds (stays in registers)
#pragma unroll
            for (int b = 0; b < NBINS; b++)
                if (bi == b) gd_acc[b] += m;
            // label histogram: 3 bins per (lane, slot), static indices
#pragma unroll
            for (int k = 0; k < 3; k++)
                if (tb == k) lab_acc[3 * e + k] += m;
        }
    }

    // ---- warp reductions ----
#pragma unroll
    for (int off = 16; off > 0; off >>= 1) {
        loss_acc += __shfl_down_sync(0xffffffffu, loss_acc, off);
        m_acc    += __shfl_down_sync(0xffffffffu, m_acc, off);
    }
    if (lane == 0) { s_loss[warp] = loss_acc; s_m[warp] = m_acc; }

#pragma unroll
    for (int b = 0; b < NBINS; b++) {
        float v = gd_acc[b];
#pragma unroll
        for (int off = 16; off > 0; off >>= 1)
            v += __shfl_down_sync(0xffffffffu, v, off);
        if (lane == 0) s_gd_stage[warp * NBINS + b] = v;
    }

    // label: lanes own disjoint bins -> plain stores, stride-13 padding (conflict-free)
#pragma unroll
    for (int k = 0; k < 12; k++)
        s_lab_stage[warp * 416 + lane * 13 + k] = lab_acc[k];

    __syncthreads();

    // ---- block -> global ----
    for (int t = tid; t < NLAB; t += 256) {
        int l = t / 12, k = t % 12;
        float v = 0.f;
#pragma unroll
        for (int w = 0; w < 8; w++) v += s_lab_stage[w * 416 + l * 13 + k];
        atomicAdd(&g_lab[t], v);
    }
    if (tid < NBINS) {
        float v = 0.f;
#pragma unroll
        for (int w = 0; w < 8; w++) v += s_gd_stage[w * NBINS + tid];
        atomicAdd(&g_gd[tid], v);
    }
    if (tid == 0) {
        float L = 0.f, M = 0.f;
#pragma unroll
        for (int w = 0; w < 8; w++) { L += s_loss[w]; M += s_m[w]; }
        atomicAdd(&g_loss, L);
        atomicAdd(&g_msum, M * 4.0f);   // each lane's m covered 4 elements
    }
}

// ---------------- finalize: loss + EMA updates, single block ----------------
__global__ __launch_bounds__(512)
void ghm_finalize_kernel(const float* __restrict__ gd_in,
                         const float* __restrict__ lab_in,
                         float* __restrict__ out)
{
    __shared__ float red[512];
    const int tid = threadIdx.x;

    // --- label hist sum ---
    float h = (tid < NLAB) ? g_lab[tid] : 0.f;
    red[tid] = h;
    __syncthreads();
#pragma unroll
    for (int s = 256; s > 0; s >>= 1) {
        if (tid < s) red[tid] += red[tid + s];
        __syncthreads();
    }
    float hsum = red[0];
    __syncthreads();

    float ema = 0.f;
    if (tid < NLAB) {
        float hn = h / fmaxf(hsum, 1e-10f) * (float)NLAB;
        ema = lab_in[tid] * 0.999f + 0.001f * hn;
    }
    red[tid] = (tid < NLAB) ? ema : 0.f;
    __syncthreads();
#pragma unroll
    for (int s = 256; s > 0; s >>= 1) {
        if (tid < s) red[tid] += red[tid + s];
        __syncthreads();
    }
    float esum = red[0];
    if (tid < NLAB)
        out[1 + NBINS + tid] = ema / fmaxf(esum, 1e-10f) * (float)NLAB;

    // --- GD ema + loss (tiny, one thread) ---
    if (tid == 0) {
        float hs = 0.f;
#pragma unroll
        for (int b = 0; b < NBINS; b++) hs += g_gd[b];
        hs = fmaxf(hs, 1e-10f);
        float e[NBINS]; float es = 0.f;
#pragma unroll
        for (int b = 0; b < NBINS; b++) {
            e[b] = gd_in[b] * 0.999f + 0.001f * (g_gd[b] / hs * (float)NBINS);
            es += e[b];
        }
        es = fmaxf(es, 1e-10f);
#pragma unroll
        for (int b = 0; b < NBINS; b++) out[1 + b] = e[b] / es * (float)NBINS;

        out[0] = g_loss / fmaxf(g_msum, 1e-10f);
    }
}

extern "C" void kernel_launch(void* const* d_in, const int* in_sizes, int n_in,
                              void* d_out, int out_size)
{
    const float* logits = (const float*)d_in[0];
    const float* tprob  = (const float*)d_in[1];
    const float* mask   = (const float*)d_in[2];
    const float* gd_ema = (const float*)d_in[3];
    const float* lab_ema= (const float*)d_in[4];

    const int total = in_sizes[0];
    const int rows  = total / NCLS;      // 65536

    ghm_init_kernel<<<1, 512>>>();
    ghm_main_kernel<<<592, 256>>>((const float4*)logits, (const float4*)tprob,
                                  mask, gd_ema, lab_ema, rows);
    ghm_finalize_kernel<<<1, 512>>>(gd_ema, lab_ema, (float*)d_out);
}

// round 2
// speedup vs baseline: 1.0206x; 1.0206x over previous
#include <cuda_runtime.h>
#include <cuda_bf16.h>

#define NBINS 10
#define NCLS  128
#define NLAB  (NCLS * 3)   // 384
#define ALPHA 0.999f

// ---------------- device scratch (self-resetting: last block zeroes after use) ----
__device__ float g_loss = 0.f;
__device__ float g_msum = 0.f;
__device__ float g_gd[NBINS] = {};
__device__ float g_lab[NLAB] = {};
__device__ unsigned int g_ticket = 0;

__device__ __forceinline__ float rcp_approx(float x) {
    float r;
    asm("rcp.approx.f32 %0, %1;" : "=f"(r) : "f"(x));
    return r;
}

// ---------------- single fused kernel: warp per row of 128 classes ----------------
// lane l handles classes 4l..4l+3 (one float4 of logits + one of targets).
__global__ __launch_bounds__(256, 4)
void ghm_fused_kernel(const float4* __restrict__ logits,
                      const float4* __restrict__ tprob,
                      const float*  __restrict__ mask,
                      const float*  __restrict__ gd_ema,
                      const float*  __restrict__ lab_ema,
                      float* __restrict__ out,
                      int rows)
{
    // weight tables laid out so every lane always hits bank == lane (conflict-free)
    __shared__ float s_gdr[NBINS * 32];     // [bi*32 + lane] = rsqrt(gd_ema[bi])
    __shared__ float s_labp[NLAB];          // [j*32 + lane]  = rsqrt(lab_ema[12*lane + j])
    __shared__ float s_lab_stage[8 * 416];  // per-warp label hist, lane stride 13
    __shared__ float s_gd_stage[8 * NBINS];
    __shared__ float s_loss[8], s_m[8];
    __shared__ float s_red[256];
    __shared__ int   s_last;

    const int tid  = threadIdx.x;
    const int lane = tid & 31;
    const int warp = tid >> 5;

    for (int i = tid; i < NBINS * 32; i += 256) s_gdr[i] = rsqrtf(__ldg(&gd_ema[i >> 5]));
    for (int i = tid; i < NLAB; i += 256)
        s_labp[i] = rsqrtf(__ldg(&lab_ema[12 * (i & 31) + (i >> 5)]));
    __syncthreads();

    const int gwarp  = blockIdx.x * 8 + warp;
    const int nwarps = gridDim.x * 8;

    float loss_acc = 0.f;
    float m_acc    = 0.f;
    float gd_acc[NBINS];
    float lab_acc[12];
#pragma unroll
    for (int b = 0; b < NBINS; b++) gd_acc[b] = 0.f;
#pragma unroll
    for (int k = 0; k < 12; k++) lab_acc[k] = 0.f;

    const float4* lp = logits + (size_t)gwarp * 32 + lane;
    const float4* tp = tprob  + (size_t)gwarp * 32 + lane;
    const float*  mp = mask + gwarp;
    const size_t  step = (size_t)nwarps * 32;

    for (int row = gwarp; row < rows; row += nwarps) {
        const float4 x4 = *lp;
        const float4 t4 = *tp;
        const float  m  = *mp;
        lp += step; tp += step; mp += nwarps;
        m_acc += m;

        float xs[4] = {x4.x, x4.y, x4.z, x4.w};
        float ts[4] = {t4.x, t4.y, t4.z, t4.w};

#pragma unroll
        for (int e = 0; e < 4; e++) {
            float x = xs[e];
            float t = __saturatef(ts[e]);

            float ax  = fabsf(x);
            float ee  = __expf(-ax);                 // exp(-|x|) in (0,1]
            float d   = 1.f + ee;
            float r   = rcp_approx(d);               // 1/(1+e) in [0.5,1]
            float sig = (x >= 0.f) ? r : 1.f - r;    // sigmoid(x)
            float raw = fmaxf(x, 0.f) - x * t + __logf(d);
            float g   = fabsf(sig - t);

            int bi = min(__float2int_rz(g * 10.f), NBINS - 1);
            int tb = min(__float2int_rz(t * 3.f), 2);

            float w = s_gdr[bi * 32 + lane] * s_labp[(3 * e + tb) * 32 + lane];
            loss_acc = fmaf(raw * w, m, loss_acc);

#pragma unroll
            for (int b = 0; b < NBINS; b++)
                if (bi == b) gd_acc[b] += m;
#pragma unroll
            for (int k = 0; k < 3; k++)
                if (tb == k) lab_acc[3 * e + k] += m;
        }
    }

    // ---- warp reductions ----
#pragma unroll
    for (int off = 16; off > 0; off >>= 1) {
        loss_acc += __shfl_down_sync(0xffffffffu, loss_acc, off);
        m_acc    += __shfl_down_sync(0xffffffffu, m_acc, off);
    }
    if (lane == 0) { s_loss[warp] = loss_acc; s_m[warp] = m_acc; }

#pragma unroll
    for (int b = 0; b < NBINS; b++) {
        float v = gd_acc[b];
#pragma unroll
        for (int off = 16; off > 0; off >>= 1)
            v += __shfl_down_sync(0xffffffffu, v, off);
        if (lane == 0) s_gd_stage[warp * NBINS + b] = v;
    }

#pragma unroll
    for (int k = 0; k < 12; k++)
        s_lab_stage[warp * 416 + lane * 13 + k] = lab_acc[k];

    __syncthreads();

    // ---- block -> global ----
    for (int t = tid; t < NLAB; t += 256) {
        int l = t / 12, k = t % 12;
        float v = 0.f;
#pragma unroll
        for (int w = 0; w < 8; w++) v += s_lab_stage[w * 416 + l * 13 + k];
        atomicAdd(&g_lab[t], v);
    }
    if (tid < NBINS) {
        float v = 0.f;
#pragma unroll
        for (int w = 0; w < 8; w++) v += s_gd_stage[w * NBINS + tid];
        atomicAdd(&g_gd[tid], v);
    }
    if (tid == 0) {
        float L = 0.f, M = 0.f;
#pragma unroll
        for (int w = 0; w < 8; w++) { L += s_loss[w]; M += s_m[w]; }
        atomicAdd(&g_loss, L);
        atomicAdd(&g_msum, M * 4.0f);   // each lane's m covered 4 elements
    }

    // ---- last-block finalize ----
    __threadfence();
    __syncthreads();
    if (tid == 0) {
        unsigned int tk = atomicAdd(&g_ticket, 1u);
        s_last = (tk == gridDim.x - 1) ? 1 : 0;
    }
    __syncthreads();
    if (!s_last) return;
    __threadfence();   // acquire side

    // label histogram EMA (384 bins over 256 threads: tid and tid+256)
    float h0 = (tid < NLAB) ? g_lab[tid] : 0.f;
    float h1 = (tid < NLAB - 256) ? g_lab[tid + 256] : 0.f;
    s_red[tid] = h0 + h1;
    __syncthreads();
#pragma unroll
    for (int s = 128; s > 0; s >>= 1) {
        if (tid < s) s_red[tid] += s_red[tid + s];
        __syncthreads();
    }
    float hsum = s_red[0];
    __syncthreads();

    float inv = (float)NLAB / fmaxf(hsum, 1e-10f);
    float ema0 = 0.f, ema1 = 0.f;
    if (tid < NLAB)       ema0 = __ldg(&lab_ema[tid])       * ALPHA + (1.f - ALPHA) * (h0 * inv);
    if (tid < NLAB - 256) ema1 = __ldg(&lab_ema[tid + 256]) * ALPHA + (1.f - ALPHA) * (h1 * inv);
    s_red[tid] = ema0 + ema1;
    __syncthreads();
#pragma unroll
    for (int s = 128; s > 0; s >>= 1) {
        if (tid < s) s_red[tid] += s_red[tid + s];
        __syncthreads();
    }
    float esum = s_red[0];
    float sc = (float)NLAB / fmaxf(esum, 1e-10f);
    if (tid < NLAB)       out[1 + NBINS + tid]       = ema0 * sc;
    if (tid < NLAB - 256) out[1 + NBINS + tid + 256] = ema1 * sc;

    // GD EMA + loss (tiny, one thread)
    if (tid == 0) {
        float gd[NBINS];
        float hs = 0.f;
#pragma unroll
        for (int b = 0; b < NBINS; b++) { gd[b] = g_gd[b]; hs += gd[b]; }
        hs = fmaxf(hs, 1e-10f);
        float e[NBINS]; float es = 0.f;
#pragma unroll
        for (int b = 0; b < NBINS; b++) {
            e[b] = __ldg(&gd_ema[b]) * ALPHA + (1.f - ALPHA) * (gd[b] / hs * (float)NBINS);
            es += e[b];
        }
        es = fmaxf(es, 1e-10f);
#pragma unroll
        for (int b = 0; b < NBINS; b++) out[1 + b] = e[b] / es * (float)NBINS;

        out[0] = g_loss / fmaxf(g_msum, 1e-10f);
    }

    // ---- reset scratch for the next launch ----
    if (tid < NLAB)       g_lab[tid] = 0.f;
    if (tid < NLAB - 256) g_lab[tid + 256] = 0.f;
    if (tid == 0) {
        g_loss = 0.f; g_msum = 0.f;
#pragma unroll
        for (int b = 0; b < NBINS; b++) g_gd[b] = 0.f;
        __threadfence();
        g_ticket = 0u;
    }
}

extern "C" void kernel_launch(void* const* d_in, const int* in_sizes, int n_in,
                              void* d_out, int out_size)
{
    const float* logits  = (const float*)d_in[0];
    const float* tprob   = (const float*)d_in[1];
    const float* mask    = (const float*)d_in[2];
    const float* gd_ema  = (const float*)d_in[3];
    const float* lab_ema = (const float*)d_in[4];

    const int total = in_sizes[0];
    const int rows  = total / NCLS;      // 65536

    ghm_fused_kernel<<<592, 256>>>((const float4*)logits, (const float4*)tprob,
                                   mask, gd_ema, lab_ema, (float*)d_out, rows);
}

// round 3
// speedup vs baseline: 2.2405x; 2.1953x over previous
#include <cuda_runtime.h>
#include <cuda_bf16.h>

#define NBINS 10
#define NCLS  128
#define NLAB  (NCLS * 3)   // 384
#define ALPHA 0.999f

// ---------------- device scratch (self-resetting: last block zeroes after use) ----
__device__ float g_loss = 0.f;
__device__ float g_msum = 0.f;
__device__ float g_gd[NBINS] = {};
__device__ float g_lab[NLAB] = {};
__device__ unsigned int g_ticket = 0;

__device__ __forceinline__ float rcp_approx(float x) {
    float r;
    asm("rcp.approx.f32 %0, %1;" : "=f"(r) : "f"(x));
    return r;
}

// ---------------- single fused kernel: warp per row of 128 classes ----------------
// lane l handles classes 4l..4l+3 (one float4 of logits + one of targets).
__global__ __launch_bounds__(256, 6)
void ghm_fused_kernel(const float4* __restrict__ logits,
                      const float4* __restrict__ tprob,
                      const float*  __restrict__ mask,
                      const float*  __restrict__ gd_ema,
                      const float*  __restrict__ lab_ema,
                      float* __restrict__ out,
                      int rows)
{
    // weight tables: bank == lane everywhere (conflict-free)
    __shared__ float s_gdr[NBINS * 32];   // [bi*32 + lane] = rsqrt(gd_ema[bi])
    __shared__ float s_labw[12 * 32];     // [j*32 + lane]  = rsqrt(lab_ema[12*lane + j])
    // lane-private histograms: [warp][bin][lane] -> bank == lane (conflict-free RMW)
    __shared__ float s_gdp[8 * NBINS * 32];   // 2560 floats
    __shared__ float s_labh[8 * 12 * 32];     // 3072 floats
    __shared__ float s_loss[8], s_m[8];
    __shared__ float s_red[NBINS * 32];       // 320 (also reused by finalize, needs 256)
    __shared__ int   s_last;

    const int tid  = threadIdx.x;
    const int lane = tid & 31;
    const int warp = tid >> 5;

    for (int i = tid; i < NBINS * 32; i += 256) s_gdr[i] = rsqrtf(__ldg(&gd_ema[i >> 5]));
    for (int i = tid; i < 12 * 32; i += 256)
        s_labw[i] = rsqrtf(__ldg(&lab_ema[12 * (i & 31) + (i >> 5)]));
    for (int i = tid; i < 8 * NBINS * 32; i += 256) s_gdp[i] = 0.f;
    for (int i = tid; i < 8 * 12 * 32;   i += 256) s_labh[i] = 0.f;
    __syncthreads();

    const int gwarp  = blockIdx.x * 8 + warp;
    const int nwarps = gridDim.x * 8;

    float loss_acc = 0.f;
    float m_acc    = 0.f;

    const int gd_base  = warp * (NBINS * 32) + lane;  // + bi*32
    const int lab_base = warp * (12 * 32) + lane;     // + (3e+tb)*32

    const float4* lp = logits + (size_t)gwarp * 32 + lane;
    const float4* tp = tprob  + (size_t)gwarp * 32 + lane;
    const float*  mp = mask + gwarp;
    const size_t  step = (size_t)nwarps * 32;

    for (int row = gwarp; row < rows; row += nwarps) {
        const float4 x4 = *lp;
        const float4 t4 = *tp;
        const float  m  = *mp;
        lp += step; tp += step; mp += nwarps;
        m_acc += m;

        float xs[4] = {x4.x, x4.y, x4.z, x4.w};
        float ts[4] = {t4.x, t4.y, t4.z, t4.w};

#pragma unroll
        for (int e = 0; e < 4; e++) {
            float x = xs[e];
            float t = __saturatef(ts[e]);

            float ax  = fabsf(x);
            float ee  = __expf(-ax);                 // exp(-|x|) in (0,1]
            float d   = 1.f + ee;
            float r   = rcp_approx(d);               // 1/(1+e) in [0.5,1]
            float sig = (x >= 0.f) ? r : 1.f - r;    // sigmoid(x)
            float raw = fmaxf(x, 0.f) - x * t + __logf(d);
            float g   = fabsf(sig - t);

            int bi = min(__float2int_rz(g * 10.f), NBINS - 1);
            int tb = min(__float2int_rz(t * 3.f), 2);
            int j  = 3 * e + tb;

            float w = s_gdr[bi * 32 + lane] * s_labw[j * 32 + lane];
            loss_acc = fmaf(raw * w, m, loss_acc);

            // lane-private histogram RMW (conflict-free, no atomics)
            s_gdp [gd_base  + bi * 32] += m;
            s_labh[lab_base + j  * 32] += m;
        }
    }

    // ---- loss / mask warp reductions ----
#pragma unroll
    for (int off = 16; off > 0; off >>= 1) {
        loss_acc += __shfl_down_sync(0xffffffffu, loss_acc, off);
        m_acc    += __shfl_down_sync(0xffffffffu, m_acc, off);
    }
    if (lane == 0) { s_loss[warp] = loss_acc; s_m[warp] = m_acc; }
    __syncthreads();

    // ---- block-level histogram reduction -> global atomics ----
    // GD: (bin,lane) pairs summed over 8 warps, then warp-reduce per bin
    if (tid < NBINS * 32) {
        float v = 0.f;
#pragma unroll
        for (int w = 0; w < 8; w++) v += s_gdp[w * (NBINS * 32) + tid];
        s_red[tid] = v;
    }
    // label: global bin t = 12*l + j  (l = lane owning it, j in [0,12))
    for (int t = tid; t < NLAB; t += 256) {
        int l = t / 12, j = t % 12;
        float v = 0.f;
#pragma unroll
        for (int w = 0; w < 8; w++) v += s_labh[w * (12 * 32) + j * 32 + l];
        atomicAdd(&g_lab[t], v);
    }
    __syncthreads();
    if (warp < NBINS) {
        float v = s_red[warp * 32 + lane];
#pragma unroll
        for (int off = 16; off > 0; off >>= 1)
            v += __shfl_down_sync(0xffffffffu, v, off);
        if (lane == 0) atomicAdd(&g_gd[warp], v);
    }
    if (tid == 0) {
        float L = 0.f, M = 0.f;
#pragma unroll
        for (int w = 0; w < 8; w++) { L += s_loss[w]; M += s_m[w]; }
        atomicAdd(&g_loss, L);
        atomicAdd(&g_msum, M * 4.0f);   // each lane's m covered 4 elements
    }

    // ---- last-block finalize ----
    __threadfence();
    __syncthreads();
    if (tid == 0) {
        unsigned int tk = atomicAdd(&g_ticket, 1u);
        s_last = (tk == gridDim.x - 1) ? 1 : 0;
    }
    __syncthreads();
    if (!s_last) return;
    __threadfence();   // acquire side

    // label histogram EMA (384 bins over 256 threads: tid and tid+256)
    float h0 = (tid < NLAB) ? g_lab[tid] : 0.f;
    float h1 = (tid < NLAB - 256) ? g_lab[tid + 256] : 0.f;
    s_red[tid] = h0 + h1;
    __syncthreads();
#pragma unroll
    for (int s = 128; s > 0; s >>= 1) {
        if (tid < s) s_red[tid] += s_red[tid + s];
        __syncthreads();
    }
    float hsum = s_red[0];
    __syncthreads();

    float inv = (float)NLAB / fmaxf(hsum, 1e-10f);
    float ema0 = 0.f, ema1 = 0.f;
    if (tid < NLAB)       ema0 = __ldg(&lab_ema[tid])       * ALPHA + (1.f - ALPHA) * (h0 * inv);
    if (tid < NLAB - 256) ema1 = __ldg(&lab_ema[tid + 256]) * ALPHA + (1.f - ALPHA) * (h1 * inv);
    s_red[tid] = ema0 + ema1;
    __syncthreads();
#pragma unroll
    for (int s = 128; s > 0; s >>= 1) {
        if (tid < s) s_red[tid] += s_red[tid + s];
        __syncthreads();
    }
    float esum = s_red[0];
    float sc = (float)NLAB / fmaxf(esum, 1e-10f);
    if (tid < NLAB)       out[1 + NBINS + tid]       = ema0 * sc;
    if (tid < NLAB - 256) out[1 + NBINS + tid + 256] = ema1 * sc;

    // GD EMA + loss (tiny, one thread)
    if (tid == 0) {
        float gd[NBINS];
        float hs = 0.f;
#pragma unroll
        for (int b = 0; b < NBINS; b++) { gd[b] = g_gd[b]; hs += gd[b]; }
        hs = fmaxf(hs, 1e-10f);
        float e[NBINS]; float es = 0.f;
#pragma unroll
        for (int b = 0; b < NBINS; b++) {
            e[b] = __ldg(&gd_ema[b]) * ALPHA + (1.f - ALPHA) * (gd[b] / hs * (float)NBINS);
            es += e[b];
        }
        es = fmaxf(es, 1e-10f);
#pragma unroll
        for (int b = 0; b < NBINS; b++) out[1 + b] = e[b] / es * (float)NBINS;

        out[0] = g_loss / fmaxf(g_msum, 1e-10f);
    }

    // ---- reset scratch for the next launch ----
    if (tid < NLAB)       g_lab[tid] = 0.f;
    if (tid < NLAB - 256) g_lab[tid + 256] = 0.f;
    if (tid == 0) {
        g_loss = 0.f; g_msum = 0.f;
#pragma unroll
        for (int b = 0; b < NBINS; b++) g_gd[b] = 0.f;
        __threadfence();
        g_ticket = 0u;
    }
}

extern "C" void kernel_launch(void* const* d_in, const int* in_sizes, int n_in,
                              void* d_out, int out_size)
{
    const float* logits  = (const float*)d_in[0];
    const float* tprob   = (const float*)d_in[1];
    const float* mask    = (const float*)d_in[2];
    const float* gd_ema  = (const float*)d_in[3];
    const float* lab_ema = (const float*)d_in[4];

    const int total = in_sizes[0];
    const int rows  = total / NCLS;      // 65536

    ghm_fused_kernel<<<148 * 6, 256>>>((const float4*)logits, (const float4*)tprob,
                                       mask, gd_ema, lab_ema, (float*)d_out, rows);
}

// round 4
// speedup vs baseline: 2.3930x; 1.0681x over previous
#include <cuda_runtime.h>
#include <cuda_bf16.h>

#define NBINS 10
#define NCLS  128
#define NLAB  (NCLS * 3)   // 384
#define ALPHA 0.999f

// ---------------- device scratch (self-resetting: last block zeroes after use) ----
__device__ float g_loss = 0.f;
__device__ float g_msum = 0.f;
__device__ float g_gd[NBINS] = {};
__device__ float g_lab[NLAB] = {};
__device__ unsigned int g_ticket = 0;

__device__ __forceinline__ float rcp_approx(float x) {
    float r;
    asm("rcp.approx.f32 %0, %1;" : "=f"(r) : "f"(x));
    return r;
}

// ---------------- single fused kernel: warp per row of 128 classes ----------------
// lane l handles classes 4l..4l+3 (one float4 of logits + one of targets).
// Row loads are software-pipelined: next row's loads issue before this row's math.
__global__ __launch_bounds__(256, 5)
void ghm_fused_kernel(const float4* __restrict__ logits,
                      const float4* __restrict__ tprob,
                      const float*  __restrict__ mask,
                      const float*  __restrict__ gd_ema,
                      const float*  __restrict__ lab_ema,
                      float* __restrict__ out,
                      int rows)
{
    // weight tables: bank == lane everywhere (conflict-free)
    __shared__ float s_gdr[NBINS * 32];   // [bi*32 + lane] = rsqrt(gd_ema[bi])
    __shared__ float s_labw[12 * 32];     // [j*32 + lane]  = rsqrt(lab_ema[12*lane + j])
    // lane-private histograms: [warp][bin][lane] -> bank == lane (conflict-free RMW)
    __shared__ float s_gdp[8 * NBINS * 32];   // 2560 floats
    __shared__ float s_labh[8 * 12 * 32];     // 3072 floats
    __shared__ float s_loss[8], s_m[8];
    __shared__ float s_red[NBINS * 32];
    __shared__ int   s_last;

    const int tid  = threadIdx.x;
    const int lane = tid & 31;
    const int warp = tid >> 5;

    for (int i = tid; i < NBINS * 32; i += 256) s_gdr[i] = rsqrtf(__ldg(&gd_ema[i >> 5]));
    for (int i = tid; i < 12 * 32; i += 256)
        s_labw[i] = rsqrtf(__ldg(&lab_ema[12 * (i & 31) + (i >> 5)]));
    for (int i = tid; i < 8 * NBINS * 32; i += 256) s_gdp[i] = 0.f;
    for (int i = tid; i < 8 * 12 * 32;   i += 256) s_labh[i] = 0.f;
    __syncthreads();

    const int gwarp  = blockIdx.x * 8 + warp;
    const int nwarps = gridDim.x * 8;

    float loss_acc = 0.f;
    float m_acc    = 0.f;

    const int gd_base  = warp * (NBINS * 32) + lane;  // + bi*32
    const int lab_base = warp * (12 * 32) + lane;     // + (3e+tb)*32

    const float4* lp = logits + (size_t)gwarp * 32 + lane;
    const float4* tp = tprob  + (size_t)gwarp * 32 + lane;
    const float*  mp = mask + gwarp;
    const size_t  step = (size_t)nwarps * 32;

    // ---- software-pipelined main loop ----
    int row = gwarp;
    float4 x4 = make_float4(0.f,0.f,0.f,0.f);
    float4 t4 = make_float4(0.f,0.f,0.f,0.f);
    float  m  = 0.f;
    if (row < rows) { x4 = *lp; t4 = *tp; m = *mp; }

    while (row < rows) {
        const int nrow = row + nwarps;
        float4 x4n, t4n; float mn;
        if (nrow < rows) {
            lp += step; tp += step; mp += nwarps;
            x4n = *lp; t4n = *tp; mn = *mp;   // issued ~400 cycles before use
        } else {
            x4n = x4; t4n = t4; mn = 0.f;
        }

        m_acc += m;
        float xs[4] = {x4.x, x4.y, x4.z, x4.w};
        float ts[4] = {t4.x, t4.y, t4.z, t4.w};

#pragma unroll
        for (int e = 0; e < 4; e++) {
            float x = xs[e];
            float t = __saturatef(ts[e]);

            float ax  = fabsf(x);
            float ee  = __expf(-ax);                 // exp(-|x|) in (0,1]
            float d   = 1.f + ee;
            float r   = rcp_approx(d);               // 1/(1+e) in [0.5,1]
            float sig = (x >= 0.f) ? r : 1.f - r;    // sigmoid(x)
            float raw = fmaxf(x, 0.f) - x * t + __logf(d);
            float g   = fabsf(sig - t);

            int bi = min(__float2int_rz(g * 10.f), NBINS - 1);
            int tb = min(__float2int_rz(t * 3.f), 2);
            int j  = 3 * e + tb;

            float w = s_gdr[bi * 32 + lane] * s_labw[j * 32 + lane];
            loss_acc = fmaf(raw * w, m, loss_acc);

            // lane-private histogram RMW (conflict-free, no atomics)
            s_gdp [gd_base  + bi * 32] += m;
            s_labh[lab_base + j  * 32] += m;
        }

        x4 = x4n; t4 = t4n; m = mn;
        row = nrow;
    }

    // ---- loss / mask warp reductions ----
#pragma unroll
    for (int off = 16; off > 0; off >>= 1) {
        loss_acc += __shfl_down_sync(0xffffffffu, loss_acc, off);
        m_acc    += __shfl_down_sync(0xffffffffu, m_acc, off);
    }
    if (lane == 0) { s_loss[warp] = loss_acc; s_m[warp] = m_acc; }
    __syncthreads();

    // ---- block-level histogram reduction -> global atomics ----
    if (tid < NBINS * 32) {
        float v = 0.f;
#pragma unroll
        for (int w = 0; w < 8; w++) v += s_gdp[w * (NBINS * 32) + tid];
        s_red[tid] = v;
    }
    for (int t = tid; t < NLAB; t += 256) {
        int l = t / 12, j = t % 12;
        float v = 0.f;
#pragma unroll
        for (int w = 0; w < 8; w++) v += s_labh[w * (12 * 32) + j * 32 + l];
        atomicAdd(&g_lab[t], v);
    }
    __syncthreads();
    if (warp < NBINS) {
        float v = s_red[warp * 32 + lane];
#pragma unroll
        for (int off = 16; off > 0; off >>= 1)
            v += __shfl_down_sync(0xffffffffu, v, off);
        if (lane == 0) atomicAdd(&g_gd[warp], v);
    }
    if (tid == 0) {
        float L = 0.f, M = 0.f;
#pragma unroll
        for (int w = 0; w < 8; w++) { L += s_loss[w]; M += s_m[w]; }
        atomicAdd(&g_loss, L);
        atomicAdd(&g_msum, M * 4.0f);   // each lane's m covered 4 elements
    }

    // ---- last-block finalize ----
    __threadfence();
    __syncthreads();
    if (tid == 0) {
        unsigned int tk = atomicAdd(&g_ticket, 1u);
        s_last = (tk == gridDim.x - 1) ? 1 : 0;
    }
    __syncthreads();
    if (!s_last) return;
    __threadfence();   // acquire side

    // label histogram EMA (384 bins over 256 threads: tid and tid+256)
    float h0 = (tid < NLAB) ? g_lab[tid] : 0.f;
    float h1 = (tid < NLAB - 256) ? g_lab[tid + 256] : 0.f;
    s_red[tid] = h0 + h1;
    __syncthreads();
#pragma unroll
    for (int s = 128; s > 0; s >>= 1) {
        if (tid < s) s_red[tid] += s_red[tid + s];
        __syncthreads();
    }
    float hsum = s_red[0];
    __syncthreads();

    float inv = (float)NLAB / fmaxf(hsum, 1e-10f);
    float ema0 = 0.f, ema1 = 0.f;
    if (tid < NLAB)       ema0 = __ldg(&lab_ema[tid])       * ALPHA + (1.f - ALPHA) * (h0 * inv);
    if (tid < NLAB - 256) ema1 = __ldg(&lab_ema[tid + 256]) * ALPHA + (1.f - ALPHA) * (h1 * inv);
    s_red[tid] = ema0 + ema1;
    __syncthreads();
#pragma unroll
    for (int s = 128; s > 0; s >>= 1) {
        if (tid < s) s_red[tid] += s_red[tid + s];
        __syncthreads();
    }
    float esum = s_red[0];
    float sc = (float)NLAB / fmaxf(esum, 1e-10f);
    if (tid < NLAB)       out[1 + NBINS + tid]       = ema0 * sc;
    if (tid < NLAB - 256) out[1 + NBINS + tid + 256] = ema1 * sc;

    // GD EMA + loss (tiny, one thread)
    if (tid == 0) {
        float gd[NBINS];
        float hs = 0.f;
#pragma unroll
        for (int b = 0; b < NBINS; b++) { gd[b] = g_gd[b]; hs += gd[b]; }
        hs = fmaxf(hs, 1e-10f);
        float e[NBINS]; float es = 0.f;
#pragma unroll
        for (int b = 0; b < NBINS; b++) {
            e[b] = __ldg(&gd_ema[b]) * ALPHA + (1.f - ALPHA) * (gd[b] / hs * (float)NBINS);
            es += e[b];
        }
        es = fmaxf(es, 1e-10f);
#pragma unroll
        for (int b = 0; b < NBINS; b++) out[1 + b] = e[b] / es * (float)NBINS;

        out[0] = g_loss / fmaxf(g_msum, 1e-10f);
    }

    // ---- reset scratch for the next launch ----
    if (tid < NLAB)       g_lab[tid] = 0.f;
    if (tid < NLAB - 256) g_lab[tid + 256] = 0.f;
    if (tid == 0) {
        g_loss = 0.f; g_msum = 0.f;
#pragma unroll
        for (int b = 0; b < NBINS; b++) g_gd[b] = 0.f;
        __threadfence();
        g_ticket = 0u;
    }
}

extern "C" void kernel_launch(void* const* d_in, const int* in_sizes, int n_in,
                              void* d_out, int out_size)
{
    const float* logits  = (const float*)d_in[0];
    const float* tprob   = (const float*)d_in[1];
    const float* mask    = (const float*)d_in[2];
    const float* gd_ema  = (const float*)d_in[3];
    const float* lab_ema = (const float*)d_in[4];

    const int total = in_sizes[0];
    const int rows  = total / NCLS;      // 65536

    ghm_fused_kernel<<<148 * 5, 256>>>((const float4*)logits, (const float4*)tprob,
                                       mask, gd_ema, lab_ema, (float*)d_out, rows);
}